// round 1
// baseline (speedup 1.0000x reference)
#include <cuda_runtime.h>

// AttentionalPropagation: x [B=64, C=512, L=4096] fp32.
// Per l: q = x[:,:,l] (64x512); S = q q^T / sqrt(C); P = softmax(S); msg = P q;
// out = x + msg (same layout).
//
// Design (SIMT fp32 baseline, built for full-sector global traffic):
//  - 1 CTA per 8 consecutive l (LT=8) -> every global ld/st is a 32B full sector.
//  - Pass 1 streams c in chunks of 32 through smem laid out [cc][lt][b]
//    (b fastest -> vectorized LDS.128 of q rows), accumulating the 64x64
//    score matrix per l in registers: 64 threads per l, each owns an 8x8 tile.
//  - Softmax fully in registers + 8-lane shfl butterflies.
//  - Pass 2 re-streams c through smem laid out [lt][b][33] (pad 33 kills bank
//    conflicts), computes msg = P q with an m-partial + shfl reduction, stages
//    msg through a pad-259 smem transpose buffer so the final store is 32B
//    sectors, and adds x from the already-staged smem copy (no 3rd read).

namespace {

constexpr int kB  = 64;
constexpr int kC  = 512;
constexpr int kL  = 4096;
constexpr int LT  = 8;            // l-positions per CTA
constexpr int CCH = 32;           // c per chunk
constexpr int NCH = kC / CCH;     // 16 chunks
constexpr int NT  = 512;          // threads per CTA

constexpr int XS2_PB = 33;              // pass-2 x buffer pitch over b (pad)
constexpr int XS2_PL = kB * XS2_PB;     // 2112 floats per l
constexpr int MB_P   = 259;             // msg transpose buffer pitch (pad: 259%32=3, coprime)

constexpr int SMEM_FLOATS = LT * XS2_PL + kB * MB_P;  // 16896 + 16576 = 33472
constexpr int SMEM_BYTES  = SMEM_FLOATS * 4;          // 133888 B (< 227 KB)

__global__ void __launch_bounds__(NT, 1)
attn_prop_kernel(const float* __restrict__ x, float* __restrict__ out) {
    extern __shared__ float sm[];
    float* xs1 = sm;                 // pass1: [cc][lt][b], 32*8*64 = 16384 floats
    float* xs2 = sm;                 // pass2: [lt][b][XS2_PB]
    float* mb  = sm + LT * XS2_PL;   // pass2 msg transpose: [b(n)][cc][lt], pitch MB_P

    const int t  = threadIdx.x;
    const int l0 = blockIdx.x * LT;
    const int g  = t >> 6;           // which l within the tile (0..7)
    const int u  = t & 63;           // thread within the l-group
    const int tn = u >> 3;           // n-tile index (0..7): rows n = tn*8 .. tn*8+7
    const int tm = u & 7;            // m-tile index (0..7): cols m = tm*8 .. tm*8+7

    float acc[8][8];
    #pragma unroll
    for (int i = 0; i < 8; i++)
        #pragma unroll
        for (int j = 0; j < 8; j++) acc[i][j] = 0.0f;

    // ------------------------------ Pass 1: S = q q^T ------------------------
    for (int ch = 0; ch < NCH; ch++) {
        const int c0 = ch * CCH;
        __syncthreads();  // previous chunk fully consumed before overwrite
        // Stage: each thread owns 4 (b,c) rows, loads 8 l's (32B = 1 sector).
        #pragma unroll
        for (int k = 0; k < (kB * CCH) / NT; k++) {
            const int r  = t + k * NT;
            const int cl = r >> 6;
            const int b  = r & 63;
            const float* gp = x + ((size_t)(b * kC + (c0 + cl)) * kL + l0);
            const float4 v0 = *(const float4*)gp;
            const float4 v1 = *(const float4*)(gp + 4);
            float* sp = xs1 + cl * (LT * kB) + b;   // [cc=cl][lt][b]
            sp[0 * kB] = v0.x; sp[1 * kB] = v0.y; sp[2 * kB] = v0.z; sp[3 * kB] = v0.w;
            sp[4 * kB] = v1.x; sp[5 * kB] = v1.y; sp[6 * kB] = v1.z; sp[7 * kB] = v1.w;
        }
        __syncthreads();
        // Compute: 8x8 register outer-product tile per thread.
        #pragma unroll 4
        for (int cc = 0; cc < CCH; cc++) {
            const float* base = xs1 + cc * (LT * kB) + g * kB;
            const float4 a0 = *(const float4*)(base + tn * 8);
            const float4 a1 = *(const float4*)(base + tn * 8 + 4);
            const float4 b0 = *(const float4*)(base + tm * 8);
            const float4 b1 = *(const float4*)(base + tm * 8 + 4);
            const float qa[8] = {a0.x, a0.y, a0.z, a0.w, a1.x, a1.y, a1.z, a1.w};
            const float qb[8] = {b0.x, b0.y, b0.z, b0.w, b1.x, b1.y, b1.z, b1.w};
            #pragma unroll
            for (int i = 0; i < 8; i++)
                #pragma unroll
                for (int j = 0; j < 8; j++)
                    acc[i][j] = fmaf(qa[i], qb[j], acc[i][j]);
        }
    }

    // ------------------------------ Softmax (registers + shfl) ---------------
    const float inv_scale = 0.044194173824159216f;  // 1/sqrt(512)
    #pragma unroll
    for (int i = 0; i < 8; i++) {
        float mx = -1e30f;
        #pragma unroll
        for (int j = 0; j < 8; j++) { acc[i][j] *= inv_scale; mx = fmaxf(mx, acc[i][j]); }
        mx = fmaxf(mx, __shfl_xor_sync(0xffffffffu, mx, 1));
        mx = fmaxf(mx, __shfl_xor_sync(0xffffffffu, mx, 2));
        mx = fmaxf(mx, __shfl_xor_sync(0xffffffffu, mx, 4));
        float s = 0.0f;
        #pragma unroll
        for (int j = 0; j < 8; j++) { acc[i][j] = __expf(acc[i][j] - mx); s += acc[i][j]; }
        s += __shfl_xor_sync(0xffffffffu, s, 1);
        s += __shfl_xor_sync(0xffffffffu, s, 2);
        s += __shfl_xor_sync(0xffffffffu, s, 4);
        const float inv = 1.0f / s;
        #pragma unroll
        for (int j = 0; j < 8; j++) acc[i][j] *= inv;   // acc is now P
    }

    // ------------------------------ Pass 2: out = x + P q --------------------
    for (int ch = 0; ch < NCH; ch++) {
        const int c0 = ch * CCH;
        __syncthreads();
        // Stage x chunk into padded [lt][b][cc] layout.
        #pragma unroll
        for (int k = 0; k < (kB * CCH) / NT; k++) {
            const int r  = t + k * NT;
            const int cl = r >> 6;
            const int b  = r & 63;
            const float* gp = x + ((size_t)(b * kC + (c0 + cl)) * kL + l0);
            const float4 v0 = *(const float4*)gp;
            const float4 v1 = *(const float4*)(gp + 4);
            float* sp = xs2 + b * XS2_PB + cl;
            sp[0 * XS2_PL] = v0.x; sp[1 * XS2_PL] = v0.y; sp[2 * XS2_PL] = v0.z; sp[3 * XS2_PL] = v0.w;
            sp[4 * XS2_PL] = v1.x; sp[5 * XS2_PL] = v1.y; sp[6 * XS2_PL] = v1.z; sp[7 * XS2_PL] = v1.w;
        }
        __syncthreads();
        // msg[n][c] = sum_m P[n][m] q[m][c]; thread sums its 8 m's, 8-lane shfl reduce.
        #pragma unroll 2
        for (int cc = 0; cc < CCH; cc++) {
            const float* qp = xs2 + g * XS2_PL + (tm * 8) * XS2_PB + cc;
            float qv[8];
            #pragma unroll
            for (int j = 0; j < 8; j++) qv[j] = qp[j * XS2_PB];
            float part[8];
            #pragma unroll
            for (int i = 0; i < 8; i++) {
                float p = acc[i][0] * qv[0];
                #pragma unroll
                for (int j = 1; j < 8; j++) p = fmaf(acc[i][j], qv[j], p);
                part[i] = p;
            }
            #pragma unroll
            for (int i = 0; i < 8; i++) {
                part[i] += __shfl_xor_sync(0xffffffffu, part[i], 1);
                part[i] += __shfl_xor_sync(0xffffffffu, part[i], 2);
                part[i] += __shfl_xor_sync(0xffffffffu, part[i], 4);
            }
            // Butterfly left full sums in all lanes; lane (tn,tm) stores n = tn*8+tm = u.
            float myv = part[0];
            #pragma unroll
            for (int i = 1; i < 8; i++) if (tm == i) myv = part[i];
            mb[u * MB_P + cc * 8 + g] = myv;   // pitch 259: conflict-free across lanes
        }
        __syncthreads();
        // Write out = x + msg, fully coalesced 32B sectors per (b,c).
        #pragma unroll
        for (int k = 0; k < (kB * CCH) / NT; k++) {
            const int r  = t + k * NT;
            const int cl = r >> 6;
            const int b  = r & 63;
            const float* mp = mb  + b * MB_P  + cl * 8;
            const float* xp = xs2 + b * XS2_PB + cl;
            float4 o0, o1;
            o0.x = xp[0 * XS2_PL] + mp[0];
            o0.y = xp[1 * XS2_PL] + mp[1];
            o0.z = xp[2 * XS2_PL] + mp[2];
            o0.w = xp[3 * XS2_PL] + mp[3];
            o1.x = xp[4 * XS2_PL] + mp[4];
            o1.y = xp[5 * XS2_PL] + mp[5];
            o1.z = xp[6 * XS2_PL] + mp[6];
            o1.w = xp[7 * XS2_PL] + mp[7];
            float* gp = out + ((size_t)(b * kC + (c0 + cl)) * kL + l0);
            *(float4*)gp       = o0;
            *(float4*)(gp + 4) = o1;
        }
    }
}

}  // namespace

extern "C" void kernel_launch(void* const* d_in, const int* in_sizes, int n_in,
                              void* d_out, int out_size) {
    (void)in_sizes; (void)n_in; (void)out_size;
    const float* x = (const float*)d_in[0];
    float* out     = (float*)d_out;

    // Idempotent; needed because dynamic smem (130.75 KB) exceeds the default.
    cudaFuncSetAttribute(attn_prop_kernel,
                         cudaFuncAttributeMaxDynamicSharedMemorySize, SMEM_BYTES);

    attn_prop_kernel<<<kL / LT, NT, SMEM_BYTES>>>(x, out);
}